// round 2
// baseline (speedup 1.0000x reference)
#include <cuda_runtime.h>
#include <cuda_fp16.h>
#include <cstdint>

#define NB 32      // batch
#define NI 2048    // input capsules
#define NK 16      // input dim
#define NJ 64      // output capsules
#define ND 32      // output dim
#define JD (NJ*ND) // 2048 flat (j,d)

// Scratch (allocation-free rule: __device__ globals)
__device__ __half g_uhat[(size_t)NB * NI * JD];  // [b][i][j*32+d]  256 MB, fp16
__device__ float  g_s[NB * JD];                  // s accumulator [b][j][d]
__device__ float  g_vsum[NB * JD];               // running sum of v across iters

// ---------------------------------------------------------------------------
// zero s before the atomic accumulations of the uhat kernel
// ---------------------------------------------------------------------------
__global__ void zero_s_kernel() {
    g_s[blockIdx.x * 256 + threadIdx.x] = 0.0f;
}

// ---------------------------------------------------------------------------
// u_hat[b,i,j,d] = sum_k W[j,i,d,k] * x[b,i,k]; also s0 += u_hat/64
// block: 4 j's (blockIdx.x) x 32 i's (blockIdx.y); 128 threads = (j_local, d)
// ---------------------------------------------------------------------------
__global__ void __launch_bounds__(128) uhat_kernel(const float* __restrict__ x,
                                                   const float* __restrict__ W) {
    const int t  = threadIdx.x;
    const int d  = t & 31;
    const int jl = t >> 5;
    const int j  = blockIdx.x * 4 + jl;
    const int i0 = blockIdx.y * 32;

    __shared__ float xs[NB * NK];  // x[:, i, :] for current i (2 KB)

    float s0a[NB];
#pragma unroll
    for (int b = 0; b < NB; b++) s0a[b] = 0.0f;

    for (int ii = 0; ii < 32; ii++) {
        const int i = i0 + ii;
        __syncthreads();
        {   // cooperative load of x[:, i, :] : 512 floats = 128 x float4
            const int b = t >> 2, kq = t & 3;
            ((float4*)xs)[t] =
                ((const float4*)x)[((size_t)b * NI + i) * (NK / 4) + kq];
        }
        __syncthreads();

        // W row for this (j, i, d): 16 contiguous floats, warp reads 2 KB coalesced
        const float4* wp = (const float4*)(W + (((size_t)j * NI + i) * ND + d) * NK);
        const float4 w0 = wp[0], w1 = wp[1], w2 = wp[2], w3 = wp[3];

        __half* uo = g_uhat + (size_t)i * JD + j * ND + d;  // + b*NI*JD per b
#pragma unroll
        for (int b = 0; b < NB; b++) {
            const float4* xb = (const float4*)(xs + b * NK);
            const float4 x0 = xb[0], x1 = xb[1], x2 = xb[2], x3 = xb[3];
            float acc;
            acc  = w0.x * x0.x; acc = fmaf(w0.y, x0.y, acc);
            acc  = fmaf(w0.z, x0.z, acc); acc = fmaf(w0.w, x0.w, acc);
            acc  = fmaf(w1.x, x1.x, acc); acc = fmaf(w1.y, x1.y, acc);
            acc  = fmaf(w1.z, x1.z, acc); acc = fmaf(w1.w, x1.w, acc);
            acc  = fmaf(w2.x, x2.x, acc); acc = fmaf(w2.y, x2.y, acc);
            acc  = fmaf(w2.z, x2.z, acc); acc = fmaf(w2.w, x2.w, acc);
            acc  = fmaf(w3.x, x3.x, acc); acc = fmaf(w3.y, x3.y, acc);
            acc  = fmaf(w3.z, x3.z, acc); acc = fmaf(w3.w, x3.w, acc);
            uo[(size_t)b * NI * JD] = __float2half_rn(acc);
            s0a[b] += acc;
        }
    }
#pragma unroll
    for (int b = 0; b < NB; b++)
        atomicAdd(&g_s[b * JD + j * ND + d], s0a[b] * (1.0f / 64.0f));
}

// ---------------------------------------------------------------------------
// squash: v = squash(s) per (b,j) row; manage vsum / output; re-zero s.
// mode 0: vsum = v, s = 0 | mode 1: vsum += v, s = 0 | mode 2: out = v
// 2048 rows, warp per row.
// ---------------------------------------------------------------------------
__global__ void __launch_bounds__(256) squash_kernel(float* __restrict__ out, int mode) {
    const int t    = threadIdx.x;
    const int lane = t & 31;
    const int row  = blockIdx.x * 8 + (t >> 5);  // [0, 2048)
    const int idx  = row * ND + lane;

    const float sv = g_s[idx];
    float sq = sv * sv;
#pragma unroll
    for (int off = 16; off > 0; off >>= 1)
        sq += __shfl_xor_sync(0xffffffffu, sq, off);
    const float scale = sq / (1.0f + sq) / sqrtf(sq + 1e-7f);
    const float v = scale * sv;

    if (mode == 0)      { g_vsum[idx] = v;  g_s[idx] = 0.0f; }
    else if (mode == 1) { g_vsum[idx] += v; g_s[idx] = 0.0f; }
    else                { out[idx] = v; }
}

// ---------------------------------------------------------------------------
// routing pass: per (b, i): logits t_j = vsum[b,j,:].u_hat[b,i,j,:],
// c = softmax_j(t), s[b,j,d] += c_j * u_hat[b,i,j,d].
// block = (b, chunk of 16 i's); 256 threads; thread t owns flat (j,d) = 8t..8t+7
// ---------------------------------------------------------------------------
__global__ void __launch_bounds__(256) route_kernel() {
    const int t  = threadIdx.x;
    const int b  = blockIdx.x;
    const int i0 = blockIdx.y * 16;

    __shared__ float tj[2][NJ];  // double-buffered logits / coupling coeffs

    // this thread's slice of vsum[b]: 8 floats
    const float4* vp = (const float4*)(g_vsum + b * JD) + 2 * t;
    const float4 va = vp[0], vb = vp[1];

    float sp[8];
#pragma unroll
    for (int n = 0; n < 8; n++) sp[n] = 0.0f;

    for (int ii = 0; ii < 16; ii++) {
        const int i   = i0 + ii;
        const int buf = ii & 1;

        // 8 fp16 u_hat values = 16 bytes, one uint4 load (coalesced 512B/warp)
        const uint4* up =
            (const uint4*)(g_uhat + ((size_t)b * NI + i) * JD) + t;
        const uint4 ur = *up;
        const float2 f0 = __half22float2(*(const __half2*)&ur.x);
        const float2 f1 = __half22float2(*(const __half2*)&ur.y);
        const float2 f2 = __half22float2(*(const __half2*)&ur.z);
        const float2 f3 = __half22float2(*(const __half2*)&ur.w);

        // partial dot over this thread's 8 d's
        float p;
        p  = f0.x * va.x; p = fmaf(f0.y, va.y, p);
        p  = fmaf(f1.x, va.z, p); p = fmaf(f1.y, va.w, p);
        p  = fmaf(f2.x, vb.x, p); p = fmaf(f2.y, vb.y, p);
        p  = fmaf(f3.x, vb.z, p); p = fmaf(f3.y, vb.w, p);
        // reduce the 4 threads sharing a j (adjacent lanes)
        p += __shfl_xor_sync(0xffffffffu, p, 1);
        p += __shfl_xor_sync(0xffffffffu, p, 2);
        if ((t & 3) == 0) tj[buf][t >> 2] = p;
        __syncthreads();

        if (t < 32) {  // warp 0: softmax over 64 j's
            float e0 = tj[buf][t], e1 = tj[buf][t + 32];
            float m = fmaxf(e0, e1);
#pragma unroll
            for (int off = 16; off > 0; off >>= 1)
                m = fmaxf(m, __shfl_xor_sync(0xffffffffu, m, off));
            float p0 = __expf(e0 - m), p1 = __expf(e1 - m);
            float ssum = p0 + p1;
#pragma unroll
            for (int off = 16; off > 0; off >>= 1)
                ssum += __shfl_xor_sync(0xffffffffu, ssum, off);
            const float inv = 1.0f / ssum;
            tj[buf][t]      = p0 * inv;
            tj[buf][t + 32] = p1 * inv;
        }
        __syncthreads();

        const float c = tj[buf][t >> 2];
        sp[0] = fmaf(c, f0.x, sp[0]); sp[1] = fmaf(c, f0.y, sp[1]);
        sp[2] = fmaf(c, f1.x, sp[2]); sp[3] = fmaf(c, f1.y, sp[3]);
        sp[4] = fmaf(c, f2.x, sp[4]); sp[5] = fmaf(c, f2.y, sp[5]);
        sp[6] = fmaf(c, f3.x, sp[6]); sp[7] = fmaf(c, f3.y, sp[7]);
    }

    float* sb = g_s + b * JD + t * 8;
#pragma unroll
    for (int n = 0; n < 8; n++) atomicAdd(sb + n, sp[n]);
}

// ---------------------------------------------------------------------------
extern "C" void kernel_launch(void* const* d_in, const int* in_sizes, int n_in,
                              void* d_out, int out_size) {
    const float* x = (const float*)d_in[0];
    const float* W = (const float*)d_in[1];
    // defensive: identify by size (x = 1,048,576; W = 67,108,864)
    if (n_in >= 2 && in_sizes[0] > in_sizes[1]) {
        x = (const float*)d_in[1];
        W = (const float*)d_in[0];
    }
    float* out = (float*)d_out;

    zero_s_kernel<<<256, 256>>>();
    uhat_kernel<<<dim3(16, 64), 128>>>(x, W);       // u_hat + s0 (uniform c)
    squash_kernel<<<256, 256>>>(out, 0);            // v0 -> vsum, s=0
    route_kernel<<<dim3(32, 128), 256>>>();         // iter 1: s1
    squash_kernel<<<256, 256>>>(out, 1);            // v1, vsum=v0+v1, s=0
    route_kernel<<<dim3(32, 128), 256>>>();         // iter 2: s2
    squash_kernel<<<256, 256>>>(out, 2);            // out = squash(s2)
}

// round 5
// speedup vs baseline: 1.2596x; 1.2596x over previous
#include <cuda_runtime.h>
#include <cuda_fp16.h>
#include <cstdint>

#define NB 32      // batch
#define NI 2048    // input capsules
#define NK 16      // input dim
#define NJ 64      // output capsules
#define ND 32      // output dim
#define JD (NJ*ND) // 2048 flat (j,d)

// Scratch (allocation-free rule: __device__ globals)
__device__ __half g_uhat[(size_t)NB * NI * JD];  // [b][i][j*32+d]  256 MB fp16
__device__ float  g_s[NB * JD];                  // s accumulator [b][j][d]
__device__ float  g_vsum[NB * JD];               // running sum of v across iters

// ---------------------------------------------------------------------------
__global__ void zero_s_kernel() {
    g_s[blockIdx.x * 256 + threadIdx.x] = 0.0f;
}

// ---------------------------------------------------------------------------
// u_hat[b,i,j,d] = sum_k W[j,i,d,k] * x[b,i,k]; fused s0 += u_hat/64.
// Thread owns a d-PAIR (d0,d0+1): shares the x loads across both d's and
// stores one __half2 (STG.32) per b instead of two STG.16.
// block: 128 thr = (jl 0..7) x (d2 0..15). grid: (8 j-blocks, 128 i-blocks of 16)
// ---------------------------------------------------------------------------
__global__ void __launch_bounds__(128) uhat_kernel(const float* __restrict__ x,
                                                   const float* __restrict__ W) {
    const int t  = threadIdx.x;
    const int d2 = t & 15;
    const int d0 = d2 * 2;
    const int jl = t >> 4;
    const int j  = blockIdx.x * 8 + jl;
    const int i0 = blockIdx.y * 16;

    __shared__ __align__(16) float4 xs[NB * 4];  // x[:, i, :] (2 KB)

    float s0a[NB], s0b[NB];
#pragma unroll
    for (int b = 0; b < NB; b++) { s0a[b] = 0.0f; s0b[b] = 0.0f; }

    for (int ii = 0; ii < 16; ii++) {
        const int i = i0 + ii;
        __syncthreads();
        {   // cooperative load of x[:, i, :] : 512 floats = 128 x float4
            const int b = t >> 2, kq = t & 3;
            xs[t] = __ldg(((const float4*)x) + ((size_t)b * NI + i) * (NK / 4) + kq);
        }
        __syncthreads();

        // W rows d0, d0+1: 32 contiguous floats = this thread's 128B line
        const float4* wp = (const float4*)(W + (((size_t)j * NI + i) * ND + d0) * NK);
        float4 w0[4], w1[4];
#pragma unroll
        for (int q = 0; q < 4; q++) { w0[q] = __ldg(wp + q); w1[q] = __ldg(wp + 4 + q); }

        __half2* uo = (__half2*)(g_uhat + (size_t)i * JD + j * ND + d0);
#pragma unroll
        for (int b = 0; b < NB; b++) {
            const float4 x0 = xs[b * 4 + 0], x1 = xs[b * 4 + 1];
            const float4 x2 = xs[b * 4 + 2], x3 = xs[b * 4 + 3];
            float a0, a1;
            a0  = w0[0].x * x0.x;           a1  = w1[0].x * x0.x;
            a0  = fmaf(w0[0].y, x0.y, a0);  a1  = fmaf(w1[0].y, x0.y, a1);
            a0  = fmaf(w0[0].z, x0.z, a0);  a1  = fmaf(w1[0].z, x0.z, a1);
            a0  = fmaf(w0[0].w, x0.w, a0);  a1  = fmaf(w1[0].w, x0.w, a1);
            a0  = fmaf(w0[1].x, x1.x, a0);  a1  = fmaf(w1[1].x, x1.x, a1);
            a0  = fmaf(w0[1].y, x1.y, a0);  a1  = fmaf(w1[1].y, x1.y, a1);
            a0  = fmaf(w0[1].z, x1.z, a0);  a1  = fmaf(w1[1].z, x1.z, a1);
            a0  = fmaf(w0[1].w, x1.w, a0);  a1  = fmaf(w1[1].w, x1.w, a1);
            a0  = fmaf(w0[2].x, x2.x, a0);  a1  = fmaf(w1[2].x, x2.x, a1);
            a0  = fmaf(w0[2].y, x2.y, a0);  a1  = fmaf(w1[2].y, x2.y, a1);
            a0  = fmaf(w0[2].z, x2.z, a0);  a1  = fmaf(w1[2].z, x2.z, a1);
            a0  = fmaf(w0[2].w, x2.w, a0);  a1  = fmaf(w1[2].w, x2.w, a1);
            a0  = fmaf(w0[3].x, x3.x, a0);  a1  = fmaf(w1[3].x, x3.x, a1);
            a0  = fmaf(w0[3].y, x3.y, a0);  a1  = fmaf(w1[3].y, x3.y, a1);
            a0  = fmaf(w0[3].z, x3.z, a0);  a1  = fmaf(w1[3].z, x3.z, a1);
            a0  = fmaf(w0[3].w, x3.w, a0);  a1  = fmaf(w1[3].w, x3.w, a1);
            s0a[b] += a0;
            s0b[b] += a1;
            uo[(size_t)b * NI * (JD / 2)] = __floats2half2_rn(a0, a1);
        }
    }
#pragma unroll
    for (int b = 0; b < NB; b++) {
        atomicAdd(&g_s[b * JD + j * ND + d0],     s0a[b] * (1.0f / 64.0f));
        atomicAdd(&g_s[b * JD + j * ND + d0 + 1], s0b[b] * (1.0f / 64.0f));
    }
}

// ---------------------------------------------------------------------------
// squash: v = squash(s) per (b,j) row; mode 0: vsum=v,s=0 | 1: vsum+=v,s=0 | 2: out=v
// ---------------------------------------------------------------------------
__global__ void __launch_bounds__(256) squash_kernel(float* __restrict__ out, int mode) {
    const int t    = threadIdx.x;
    const int lane = t & 31;
    const int row  = blockIdx.x * 8 + (t >> 5);
    const int idx  = row * ND + lane;

    const float sv = g_s[idx];
    float sq = sv * sv;
#pragma unroll
    for (int off = 16; off > 0; off >>= 1)
        sq += __shfl_xor_sync(0xffffffffu, sq, off);
    const float scale = sq / (1.0f + sq) / sqrtf(sq + 1e-7f);
    const float v = scale * sv;

    if (mode == 0)      { g_vsum[idx] = v;  g_s[idx] = 0.0f; }
    else if (mode == 1) { g_vsum[idx] += v; g_s[idx] = 0.0f; }
    else                { out[idx] = v; }
}

// ---------------------------------------------------------------------------
// routing pass. block = (b, 16 i's); 256 thr; thread owns flat (j,d) 8t..8t+7.
// Software-pipelined u_hat prefetch; ONE barrier/iter; softmax redundantly
// per-warp (broadcast LDS + shfl), coupling coeff fetched via shfl.
// ---------------------------------------------------------------------------
__global__ void __launch_bounds__(256) route_kernel() {
    const int t    = threadIdx.x;
    const int lane = t & 31;
    const int w    = t >> 5;
    const int b    = blockIdx.x;
    const int i0   = blockIdx.y * 16;
    const int jj   = 8 * w + (lane >> 2);   // this thread's output capsule j

    __shared__ float tj[2][NJ];  // double-buffered logits

    const float4* vp = (const float4*)(g_vsum + b * JD) + 2 * t;
    const float4 va = vp[0], vb = vp[1];

    float sp[8];
#pragma unroll
    for (int n = 0; n < 8; n++) sp[n] = 0.0f;

    const uint4* ubase = (const uint4*)(g_uhat + ((size_t)b * NI + i0) * JD) + t;
    uint4 ur = ubase[0];   // prefetch i0

#pragma unroll 4
    for (int ii = 0; ii < 16; ii++) {
        const int buf = ii & 1;
        uint4 un;
        if (ii < 15) un = ubase[(ii + 1) * (JD / 8)];   // prefetch next i early

        const float2 f0 = __half22float2(*(const __half2*)&ur.x);
        const float2 f1 = __half22float2(*(const __half2*)&ur.y);
        const float2 f2 = __half22float2(*(const __half2*)&ur.z);
        const float2 f3 = __half22float2(*(const __half2*)&ur.w);

        // partial logit over this thread's 8 d's
        float p;
        p  = f0.x * va.x; p = fmaf(f0.y, va.y, p);
        p  = fmaf(f1.x, va.z, p); p = fmaf(f1.y, va.w, p);
        p  = fmaf(f2.x, vb.x, p); p = fmaf(f2.y, vb.y, p);
        p  = fmaf(f3.x, vb.z, p); p = fmaf(f3.y, vb.w, p);
        p += __shfl_xor_sync(0xffffffffu, p, 1);
        p += __shfl_xor_sync(0xffffffffu, p, 2);
        if ((t & 3) == 0) tj[buf][t >> 2] = p;
        __syncthreads();

        // every warp computes the softmax over 64 j's from smem (broadcast LDS)
        const float e0 = tj[buf][lane], e1 = tj[buf][lane + 32];
        float m = fmaxf(e0, e1);
#pragma unroll
        for (int off = 16; off > 0; off >>= 1)
            m = fmaxf(m, __shfl_xor_sync(0xffffffffu, m, off));
        const float p0 = __expf(e0 - m), p1 = __expf(e1 - m);
        float ssum = p0 + p1;
#pragma unroll
        for (int off = 16; off > 0; off >>= 1)
            ssum += __shfl_xor_sync(0xffffffffu, ssum, off);
        const float inv = 1.0f / ssum;
        // c[jj]: lane (jj&31) holds it in p0 (jj<32) or p1 (jj>=32); w-uniform branch
        const float csel = (w < 4) ? p0 : p1;
        const float cj = __shfl_sync(0xffffffffu, csel * inv, jj & 31);

        sp[0] = fmaf(cj, f0.x, sp[0]); sp[1] = fmaf(cj, f0.y, sp[1]);
        sp[2] = fmaf(cj, f1.x, sp[2]); sp[3] = fmaf(cj, f1.y, sp[3]);
        sp[4] = fmaf(cj, f2.x, sp[4]); sp[5] = fmaf(cj, f2.y, sp[5]);
        sp[6] = fmaf(cj, f3.x, sp[6]); sp[7] = fmaf(cj, f3.y, sp[7]);
        ur = un;
    }

    float* sb = g_s + b * JD + t * 8;
#pragma unroll
    for (int n = 0; n < 8; n++) atomicAdd(sb + n, sp[n]);
}

// ---------------------------------------------------------------------------
extern "C" void kernel_launch(void* const* d_in, const int* in_sizes, int n_in,
                              void* d_out, int out_size) {
    const float* x = (const float*)d_in[0];
    const float* W = (const float*)d_in[1];
    if (n_in >= 2 && in_sizes[0] > in_sizes[1]) {   // identify by size
        x = (const float*)d_in[1];
        W = (const float*)d_in[0];
    }
    float* out = (float*)d_out;

    zero_s_kernel<<<256, 256>>>();
    uhat_kernel<<<dim3(8, 128), 128>>>(x, W);       // u_hat + s0 (uniform c)
    squash_kernel<<<256, 256>>>(out, 0);            // v0 -> vsum, s=0
    route_kernel<<<dim3(32, 128), 256>>>();         // iter 1: s1
    squash_kernel<<<256, 256>>>(out, 1);            // v1, vsum=v0+v1, s=0
    route_kernel<<<dim3(32, 128), 256>>>();         // iter 2: s2
    squash_kernel<<<256, 256>>>(out, 2);            // out = squash(s2)
}